// round 13
// baseline (speedup 1.0000x reference)
#include <cuda_runtime.h>
#include <cuda_fp16.h>

#define NUM_ENTITIES 200000
#define NEG_INF -9e15f
#define ALPHA 0.2f
#define DDIM 64
#define MNB 16
#define NREL 51
#define FULLMASK 0xffffffffu

// Fused per-relation projection table in fp16, 16B per lane (lanes 0..15):
// g_uh[r*128 + l*8 + {0..3}] = u1[4l..4l+3], g_uh[r*128 + l*8 + {4..7}] = u2[4l..4l+3]
// where u1[k] = sum_d fc_W[k,d]*rel[r,d], u2[k] = sum_d fc_W[k+64,d]*rel[r,d].
__device__ __align__(16) __half g_uh[NREL * 2 * DDIM];
__device__ float g_c[NREL];           // c[r] = dot(fc_b, rel[r])

// 51 blocks x 64 threads: thread k computes u1[k], u2[k] for relation r.
__global__ void precompute_kernel(const float* __restrict__ fc_W,
                                  const float* __restrict__ fc_b,
                                  const float* __restrict__ rel_table) {
    __shared__ float rel[DDIM];
    const int r = blockIdx.x;
    const int k = threadIdx.x;

    const float rv_k = rel_table[r * DDIM + k];
    rel[k] = rv_k;
    __syncthreads();

    float s1 = 0.f, s2 = 0.f;
#pragma unroll 8
    for (int d = 0; d < DDIM; d++) {
        float rv = rel[d];
        s1 = fmaf(fc_W[k * DDIM + d], rv, s1);
        s2 = fmaf(fc_W[(k + DDIM) * DDIM + d], rv, s2);
    }
    const int base = r * 2 * DDIM + (k >> 2) * 8 + (k & 3);
    g_uh[base]     = __float2half(s1);
    g_uh[base + 4] = __float2half(s2);

    float bp = fc_b[k] * rv_k;
    bp += __shfl_xor_sync(FULLMASK, bp, 16);
    bp += __shfl_xor_sync(FULLMASK, bp, 8);
    bp += __shfl_xor_sync(FULLMASK, bp, 4);
    bp += __shfl_xor_sync(FULLMASK, bp, 2);
    bp += __shfl_xor_sync(FULLMASK, bp, 1);
    __shared__ float warp_sum[2];
    if ((k & 31) == 0) warp_sum[k >> 5] = bp;
    __syncthreads();
    if (k == 0) g_c[r] = warp_sum[0] + warp_sum[1];
}

// Grid-stride persistent kernel: TWO adjacent rows per warp per iteration,
// phase-interleaved so both rows' loads batch together (2x MLP) and the two
// independent shfl-reduction chains hide each other's latency.
// Lane owns dims [4*(lane&15)..+3]; lanes 0-15 even neighbors, 16-31 odd.
__global__ void __launch_bounds__(256, 3)
gat_kernel(const int* __restrict__ item_ids,
           const int* __restrict__ item_entities,
           const int* __restrict__ item_relations,
           const float* __restrict__ item_table,
           const float* __restrict__ entity_table,
           float* __restrict__ out,
           int N) {
    const int lane  = threadIdx.x & 31;
    const int half  = lane >> 4;
    const int dlane = lane & 15;
    const bool b3 = lane & 8, b2 = lane & 4, b1 = lane & 2;
    const int v = 2 * ((b3 ? 4 : 0) | (b2 ? 2 : 0) | (b1 ? 1 : 0)) + half;

    const int pair0   = blockIdx.x * 8 + (threadIdx.x >> 5);
    const int pstride = gridDim.x * 8;
    const int npairs  = (N + 1) >> 1;

    for (int p = pair0; p < npairs; p += pstride) {
        int row[2];
        row[0] = 2 * p;
        row[1] = (2 * p + 1 < N) ? (2 * p + 1) : (N - 1);

        // ---- Batched scalar loads for both rows ----
        int my_id[2], iid[2];
#pragma unroll
        for (int j = 0; j < 2; j++) {
            const int* idp = (lane < MNB)
                ? (item_entities + row[j] * MNB + lane)
                : (item_relations + row[j] * MNB + lane - MNB);
            my_id[j] = __ldg(idp);
            iid[j]   = __ldg(item_ids + row[j]);
        }
        __half2 it_h[2][2];
#pragma unroll
        for (int j = 0; j < 2; j++) {
            const float4 it = *(const float4*)(item_table + iid[j] * DDIM + 4 * dlane);
            it_h[j][0] = __floats2half2_rn(it.x, it.y);
            it_h[j][1] = __floats2half2_rn(it.z, it.w);
        }

        // ---- Phase 1: 16 paired gathers (both rows), pack to fp16 ----
        __half2 ent_h[2][8][2];
#pragma unroll
        for (int i = 0; i < 8; i++) {
#pragma unroll
            for (int j = 0; j < 2; j++) {
                const int eid = __shfl_sync(FULLMASK, my_id[j], 2 * i + half);
                const float4 e = *(const float4*)(entity_table + eid * DDIM + 4 * dlane);
                ent_h[j][i][0] = __floats2half2_rn(e.x, e.y);
                ent_h[j][i][1] = __floats2half2_rn(e.z, e.w);
            }
        }

        // ---- Phase 1b: u-table loads + fp16 partial dots (both rows) ----
        float pl[2][8];
#pragma unroll
        for (int i = 0; i < 8; i++) {
#pragma unroll
            for (int j = 0; j < 2; j++) {
                const int rid = __shfl_sync(FULLMASK, my_id[j], MNB + 2 * i + half);
                const uint4 u = *(const uint4*)(g_uh + rid * 2 * DDIM + 8 * dlane);
                __half2 h1 = __hmul2(*(const __half2*)&u.x, it_h[j][0]);
                h1 = __hfma2(*(const __half2*)&u.y, it_h[j][1], h1);
                __half2 h2 = __hmul2(*(const __half2*)&u.z, ent_h[j][i][0]);
                h2 = __hfma2(*(const __half2*)&u.w, ent_h[j][i][1], h2);
                h1 = __hadd2(h1, h2);
                const float2 pf = __half22float2(h1);
                pl[j][i] = pf.x + pf.y;
            }
        }

        // ---- Phase 2: two interleaved merge trees (lane bits {3,2,1} + bit 0).
        // Lane l ends with value idx = 4*b3+2*b2+b1 of each row; v = 2*idx+half.
#pragma unroll
        for (int i = 0; i < 4; i++) {
#pragma unroll
            for (int j = 0; j < 2; j++) {
                float a = pl[j][i]     + __shfl_xor_sync(FULLMASK, pl[j][i],     8);
                float b = pl[j][i + 4] + __shfl_xor_sync(FULLMASK, pl[j][i + 4], 8);
                pl[j][i] = b3 ? b : a;
            }
        }
#pragma unroll
        for (int i = 0; i < 2; i++) {
#pragma unroll
            for (int j = 0; j < 2; j++) {
                float a = pl[j][i]     + __shfl_xor_sync(FULLMASK, pl[j][i],     4);
                float b = pl[j][i + 2] + __shfl_xor_sync(FULLMASK, pl[j][i + 2], 4);
                pl[j][i] = b2 ? b : a;
            }
        }
        float e[2];
#pragma unroll
        for (int j = 0; j < 2; j++) {
            float a0 = pl[j][0] + __shfl_xor_sync(FULLMASK, pl[j][0], 2);
            float b0 = pl[j][1] + __shfl_xor_sync(FULLMASK, pl[j][1], 2);
            float t = b1 ? b0 : a0;
            e[j] = t + __shfl_xor_sync(FULLMASK, t, 1);
        }

        // ---- Epilogue logits (one per lane per row) ----
#pragma unroll
        for (int j = 0; j < 2; j++) {
            const int rid_v = __shfl_sync(FULLMASK, my_id[j], MNB + v);
            const int eid_v = __shfl_sync(FULLMASK, my_id[j], v);
            float t = e[j] + __ldg(g_c + rid_v);
            t = (t > 0.f) ? t : ALPHA * t;
            e[j] = (eid_v != NUM_ENTITIES) ? t : NEG_INF;
        }

        // ---- Two interleaved softmaxes over lane bits {1,2,3,4} ----
        float mx[2] = {e[0], e[1]};
#pragma unroll
        for (int o = 2; o <= 16; o <<= 1) {
#pragma unroll
            for (int j = 0; j < 2; j++)
                mx[j] = fmaxf(mx[j], __shfl_xor_sync(FULLMASK, mx[j], o));
        }
        float ex[2], s[2];
#pragma unroll
        for (int j = 0; j < 2; j++) { ex[j] = __expf(e[j] - mx[j]); s[j] = ex[j]; }
#pragma unroll
        for (int o = 2; o <= 16; o <<= 1) {
#pragma unroll
            for (int j = 0; j < 2; j++)
                s[j] += __shfl_xor_sync(FULLMASK, s[j], o);
        }
        float w[2];
#pragma unroll
        for (int j = 0; j < 2; j++) w[j] = __fdividef(ex[j], s[j]);

        // ---- Weighted sums (sequential per row to cap register peak) ----
#pragma unroll
        for (int j = 0; j < 2; j++) {
            float4 acc = make_float4(0.f, 0.f, 0.f, 0.f);
#pragma unroll
            for (int i = 0; i < 8; i++) {
                const int ii = (((i >> 2) & 1) << 3) | (((i >> 1) & 1) << 2) | ((i & 1) << 1);
                const float wm = __shfl_sync(FULLMASK, w[j], ii + (lane & 16));
                const float2 exy = __half22float2(ent_h[j][i][0]);
                const float2 ezw = __half22float2(ent_h[j][i][1]);
                acc.x = fmaf(wm, exy.x, acc.x);
                acc.y = fmaf(wm, exy.y, acc.y);
                acc.z = fmaf(wm, ezw.x, acc.z);
                acc.w = fmaf(wm, ezw.y, acc.w);
            }
            acc.x += __shfl_xor_sync(FULLMASK, acc.x, 16);
            acc.y += __shfl_xor_sync(FULLMASK, acc.y, 16);
            acc.z += __shfl_xor_sync(FULLMASK, acc.z, 16);
            acc.w += __shfl_xor_sync(FULLMASK, acc.w, 16);
            if (lane < 16 && (j == 0 || 2 * p + 1 < N)) {
                // Reload the item vector (fp32, exact) for the residual.
                const float4 itf = *(const float4*)(item_table + iid[j] * DDIM + 4 * dlane);
                acc.x += itf.x; acc.y += itf.y; acc.z += itf.z; acc.w += itf.w;
                *(float4*)(out + row[j] * DDIM + 4 * dlane) = acc;
            }
        }
    }
}

extern "C" void kernel_launch(void* const* d_in, const int* in_sizes, int n_in,
                              void* d_out, int out_size) {
    const int*   item_ids       = (const int*)d_in[0];
    const int*   item_entities  = (const int*)d_in[1];
    const int*   item_relations = (const int*)d_in[2];
    const float* item_table     = (const float*)d_in[3];
    const float* entity_table   = (const float*)d_in[4];
    const float* relation_table = (const float*)d_in[5];
    const float* fc_W           = (const float*)d_in[6];
    const float* fc_b           = (const float*)d_in[7];
    float* out = (float*)d_out;

    const int N = in_sizes[0];

    precompute_kernel<<<NREL, DDIM>>>(fc_W, fc_b, relation_table);

    // Persistent grid-stride: 3 blocks/SM x 148 SMs.
    gat_kernel<<<444, 256>>>(item_ids, item_entities, item_relations,
                             item_table, entity_table, out, N);
}

// round 14
// speedup vs baseline: 1.2715x; 1.2715x over previous
#include <cuda_runtime.h>
#include <cuda_fp16.h>

#define NUM_ENTITIES 200000
#define NEG_INF -9e15f
#define ALPHA 0.2f
#define DDIM 64
#define MNB 16
#define NREL 51
#define FULLMASK 0xffffffffu

// Fused per-relation projection table in fp16, 16B per lane (lanes 0..15):
// g_uh[r*128 + l*8 + {0..3}] = u1[4l..4l+3], g_uh[r*128 + l*8 + {4..7}] = u2[4l..4l+3]
__device__ __align__(16) __half g_uh[NREL * 2 * DDIM];
__device__ float g_c[NREL];           // c[r] = dot(fc_b, rel[r])

__global__ void precompute_kernel(const float* __restrict__ fc_W,
                                  const float* __restrict__ fc_b,
                                  const float* __restrict__ rel_table) {
    __shared__ float rel[DDIM];
    const int r = blockIdx.x;
    const int k = threadIdx.x;

    const float rv_k = rel_table[r * DDIM + k];
    rel[k] = rv_k;
    __syncthreads();

    float s1 = 0.f, s2 = 0.f;
#pragma unroll 8
    for (int d = 0; d < DDIM; d++) {
        float rv = rel[d];
        s1 = fmaf(fc_W[k * DDIM + d], rv, s1);
        s2 = fmaf(fc_W[(k + DDIM) * DDIM + d], rv, s2);
    }
    const int base = r * 2 * DDIM + (k >> 2) * 8 + (k & 3);
    g_uh[base]     = __float2half(s1);
    g_uh[base + 4] = __float2half(s2);

    float bp = fc_b[k] * rv_k;
    bp += __shfl_xor_sync(FULLMASK, bp, 16);
    bp += __shfl_xor_sync(FULLMASK, bp, 8);
    bp += __shfl_xor_sync(FULLMASK, bp, 4);
    bp += __shfl_xor_sync(FULLMASK, bp, 2);
    bp += __shfl_xor_sync(FULLMASK, bp, 1);
    __shared__ float warp_sum[2];
    if ((k & 31) == 0) warp_sum[k >> 5] = bp;
    __syncthreads();
    if (k == 0) g_c[r] = warp_sum[0] + warp_sum[1];
}

template <int n>
__device__ __forceinline__ void cp_wait() {
    asm volatile("cp.async.wait_group %0;" :: "n"(n) : "memory");
}

// Issue the 16 entity-vector copies for one row into a per-warp smem buffer.
// Lane (half, dlane) copies 16B of entity 2i+half, dims [4*dlane..+3].
// Each lane later reads back ONLY its own bytes -> per-thread wait suffices.
__device__ __forceinline__ void issue_tiles(float4 (*buf)[16], int ids,
                                            const float* __restrict__ etab,
                                            int half, int dlane) {
#pragma unroll
    for (int i = 0; i < 8; i++) {
        const int eid = __shfl_sync(FULLMASK, ids, 2 * i + half);
        const float4* src = (const float4*)(etab + eid * DDIM) + dlane;
        const unsigned dst =
            (unsigned)__cvta_generic_to_shared(&buf[2 * i + half][dlane]);
        asm volatile("cp.async.cg.shared.global [%0], [%1], 16;"
                     :: "r"(dst), "l"(src) : "memory");
    }
    asm volatile("cp.async.commit_group;" ::: "memory");
}

// Persistent kernel, 4 warps/block, one row per warp per iteration.
// Entity vectors double-buffered in per-warp smem via cp.async: the next
// row's gathers overlap the current row's compute. Lane owns dims
// [4*(lane&15)..+3]; lanes 0-15 even neighbors, 16-31 odd.
__global__ void __launch_bounds__(128, 7)
gat_kernel(const int* __restrict__ item_ids,
           const int* __restrict__ item_entities,
           const int* __restrict__ item_relations,
           const float* __restrict__ item_table,
           const float* __restrict__ entity_table,
           float* __restrict__ out,
           int N) {
    __shared__ float4 sbuf[4][2][MNB][16];   // 32 KB

    const int wid   = threadIdx.x >> 5;
    const int lane  = threadIdx.x & 31;
    const int half  = lane >> 4;
    const int dlane = lane & 15;
    const bool b3 = lane & 8, b2 = lane & 4, b1 = lane & 2;
    const int v = 2 * ((b3 ? 4 : 0) | (b2 ? 2 : 0) | (b1 ? 1 : 0)) + half;

    int row = blockIdx.x * 4 + wid;
    const int stride = gridDim.x * 4;
    if (row >= N) return;

    // ---- Prologue: stage row's tiles, prefetch next row's ids ----
    const int* idp = (lane < MNB) ? item_entities : (item_relations - MNB);
    int my_id = __ldg(idp + row * MNB + lane);
    int iid   = __ldg(item_ids + row);
    issue_tiles(sbuf[wid][0], my_id, entity_table, half, dlane);

    int next = row + stride;
    int my_id_n = 0, iid_n = 0;
    if (next < N) {
        my_id_n = __ldg(idp + next * MNB + lane);
        iid_n   = __ldg(item_ids + next);
    }
    int buf = 0;

    while (true) {
        const bool has_next = next < N;
        // Stage next row into the other buffer (overlaps this row's compute).
        if (has_next)
            issue_tiles(sbuf[wid][buf ^ 1], my_id_n, entity_table, half, dlane);
        // Prefetch ids two rows ahead.
        const int next2 = next + stride;
        int my_id_n2 = 0, iid_n2 = 0;
        if (has_next && next2 < N) {
            my_id_n2 = __ldg(idp + next2 * MNB + lane);
            iid_n2   = __ldg(item_ids + next2);
        }
        // Wait for THIS row's copies (leave next row's group in flight).
        if (has_next) cp_wait<1>(); else cp_wait<0>();

        // ---- Compute current row ----
        const float4 it = *(const float4*)(item_table + iid * DDIM + 4 * dlane);
        const __half2 it_h0 = __floats2half2_rn(it.x, it.y);
        const __half2 it_h1 = __floats2half2_rn(it.z, it.w);

        float pl[8];
#pragma unroll
        for (int i = 0; i < 8; i++) {
            const float4 ev = sbuf[wid][buf][2 * i + half][dlane];
            const int rid = __shfl_sync(FULLMASK, my_id, MNB + 2 * i + half);
            const uint4 u = *(const uint4*)(g_uh + rid * 2 * DDIM + 8 * dlane);
            __half2 h1 = __hmul2(*(const __half2*)&u.x, it_h0);
            h1 = __hfma2(*(const __half2*)&u.y, it_h1, h1);
            __half2 h2 = __hmul2(*(const __half2*)&u.z, __floats2half2_rn(ev.x, ev.y));
            h2 = __hfma2(*(const __half2*)&u.w, __floats2half2_rn(ev.z, ev.w), h2);
            h1 = __hadd2(h1, h2);
            const float2 pf = __half22float2(h1);
            pl[i] = pf.x + pf.y;
        }

        // Merge tree over lane bits {3,2,1}; butterfly over bit 0.
#pragma unroll
        for (int i = 0; i < 4; i++) {
            float a = pl[i]     + __shfl_xor_sync(FULLMASK, pl[i],     8);
            float b = pl[i + 4] + __shfl_xor_sync(FULLMASK, pl[i + 4], 8);
            pl[i] = b3 ? b : a;
        }
#pragma unroll
        for (int i = 0; i < 2; i++) {
            float a = pl[i]     + __shfl_xor_sync(FULLMASK, pl[i],     4);
            float b = pl[i + 2] + __shfl_xor_sync(FULLMASK, pl[i + 2], 4);
            pl[i] = b2 ? b : a;
        }
        float a0 = pl[0] + __shfl_xor_sync(FULLMASK, pl[0], 2);
        float b0 = pl[1] + __shfl_xor_sync(FULLMASK, pl[1], 2);
        float e = b1 ? b0 : a0;
        e += __shfl_xor_sync(FULLMASK, e, 1);

        // Epilogue logit for this lane's value v.
        const int rid_v = __shfl_sync(FULLMASK, my_id, MNB + v);
        const int eid_v = __shfl_sync(FULLMASK, my_id, v);
        e += __ldg(g_c + rid_v);
        e = (e > 0.f) ? e : ALPHA * e;
        e = (eid_v != NUM_ENTITIES) ? e : NEG_INF;

        // Softmax over the 16 values (v spans lane bits {1,2,3,4}).
        float mx = e;
        mx = fmaxf(mx, __shfl_xor_sync(FULLMASK, mx, 2));
        mx = fmaxf(mx, __shfl_xor_sync(FULLMASK, mx, 4));
        mx = fmaxf(mx, __shfl_xor_sync(FULLMASK, mx, 8));
        mx = fmaxf(mx, __shfl_xor_sync(FULLMASK, mx, 16));
        const float ex = __expf(e - mx);
        float s = ex;
        s += __shfl_xor_sync(FULLMASK, s, 2);
        s += __shfl_xor_sync(FULLMASK, s, 4);
        s += __shfl_xor_sync(FULLMASK, s, 8);
        s += __shfl_xor_sync(FULLMASK, s, 16);
        const float w = __fdividef(ex, s);

        // Weighted sum (fp32 from smem) + residual.
        float4 acc = make_float4(0.f, 0.f, 0.f, 0.f);
#pragma unroll
        for (int i = 0; i < 8; i++) {
            const int ii = (((i >> 2) & 1) << 3) | (((i >> 1) & 1) << 2) | ((i & 1) << 1);
            const float wm = __shfl_sync(FULLMASK, w, ii + (lane & 16));
            const float4 ev = sbuf[wid][buf][2 * i + half][dlane];
            acc.x = fmaf(wm, ev.x, acc.x);
            acc.y = fmaf(wm, ev.y, acc.y);
            acc.z = fmaf(wm, ev.z, acc.z);
            acc.w = fmaf(wm, ev.w, acc.w);
        }
        acc.x += __shfl_xor_sync(FULLMASK, acc.x, 16);
        acc.y += __shfl_xor_sync(FULLMASK, acc.y, 16);
        acc.z += __shfl_xor_sync(FULLMASK, acc.z, 16);
        acc.w += __shfl_xor_sync(FULLMASK, acc.w, 16);
        if (lane < 16) {
            acc.x += it.x; acc.y += it.y; acc.z += it.z; acc.w += it.w;
            *(float4*)(out + row * DDIM + 4 * dlane) = acc;
        }

        if (!has_next) break;
        row = next; my_id = my_id_n; iid = iid_n;
        my_id_n = my_id_n2; iid_n = iid_n2;
        next = next2; buf ^= 1;
    }
}

extern "C" void kernel_launch(void* const* d_in, const int* in_sizes, int n_in,
                              void* d_out, int out_size) {
    const int*   item_ids       = (const int*)d_in[0];
    const int*   item_entities  = (const int*)d_in[1];
    const int*   item_relations = (const int*)d_in[2];
    const float* item_table     = (const float*)d_in[3];
    const float* entity_table   = (const float*)d_in[4];
    const float* relation_table = (const float*)d_in[5];
    const float* fc_W           = (const float*)d_in[6];
    const float* fc_b           = (const float*)d_in[7];
    float* out = (float*)d_out;

    const int N = in_sizes[0];

    precompute_kernel<<<NREL, DDIM>>>(fc_W, fc_b, relation_table);

    // Persistent: 7 blocks/SM x 148 SMs, 4 warps/block.
    gat_kernel<<<1036, 128>>>(item_ids, item_entities, item_relations,
                              item_table, entity_table, out, N);
}

// round 16
// speedup vs baseline: 2.0519x; 1.6137x over previous
#include <cuda_runtime.h>
#include <cuda_fp16.h>

#define NUM_ENTITIES 200000
#define NEG_INF -9e15f
#define ALPHA 0.2f
#define DDIM 64
#define MNB 16
#define NREL 51
#define FULLMASK 0xffffffffu

// Fused per-relation projection table in fp16, 16B per lane (lanes 0..15):
// g_uh[r*128 + l*8 + {0..3}] = u1[4l..4l+3], g_uh[r*128 + l*8 + {4..7}] = u2[4l..4l+3]
// where u1[k] = sum_d fc_W[k,d]*rel[r,d], u2[k] = sum_d fc_W[k+64,d]*rel[r,d].
__device__ __align__(16) __half g_uh[NREL * 2 * DDIM];
__device__ float g_c[NREL];           // c[r] = dot(fc_b, rel[r])

// 51 blocks x 64 threads: thread k computes u1[k], u2[k] for relation r.
__global__ void precompute_kernel(const float* __restrict__ fc_W,
                                  const float* __restrict__ fc_b,
                                  const float* __restrict__ rel_table) {
    __shared__ float rel[DDIM];
    const int r = blockIdx.x;
    const int k = threadIdx.x;

    const float rv_k = rel_table[r * DDIM + k];
    rel[k] = rv_k;
    __syncthreads();

    float s1 = 0.f, s2 = 0.f;
#pragma unroll 8
    for (int d = 0; d < DDIM; d++) {
        float rv = rel[d];
        s1 = fmaf(fc_W[k * DDIM + d], rv, s1);
        s2 = fmaf(fc_W[(k + DDIM) * DDIM + d], rv, s2);
    }
    const int base = r * 2 * DDIM + (k >> 2) * 8 + (k & 3);
    g_uh[base]     = __float2half(s1);
    g_uh[base + 4] = __float2half(s2);

    float bp = fc_b[k] * rv_k;
    bp += __shfl_xor_sync(FULLMASK, bp, 16);
    bp += __shfl_xor_sync(FULLMASK, bp, 8);
    bp += __shfl_xor_sync(FULLMASK, bp, 4);
    bp += __shfl_xor_sync(FULLMASK, bp, 2);
    bp += __shfl_xor_sync(FULLMASK, bp, 1);
    __shared__ float warp_sum[2];
    if ((k & 31) == 0) warp_sum[k >> 5] = bp;
    __syncthreads();
    if (k == 0) g_c[r] = warp_sum[0] + warp_sum[1];
}

// Grid-stride persistent kernel: one warp per item row per iteration, with
// the NEXT iteration's neighbor/item ids prefetched at the top of the current
// iteration so each row's gathers can issue immediately.
// Lane owns dims [4*(lane&15)..+3]; lanes 0-15 even neighbors, 16-31 odd.
// fp16 partial dot (HFMA2); cross-lane accumulation/softmax/output in fp32.
__global__ void __launch_bounds__(256, 4)
gat_kernel(const int* __restrict__ item_ids,
           const int* __restrict__ item_entities,
           const int* __restrict__ item_relations,
           const float* __restrict__ item_table,
           const float* __restrict__ entity_table,
           float* __restrict__ out,
           int N) {
    const int lane  = threadIdx.x & 31;
    const int half  = lane >> 4;
    const int dlane = lane & 15;
    const bool b3 = lane & 8, b2 = lane & 4, b1 = lane & 2;
    const int v = 2 * ((b3 ? 4 : 0) | (b2 ? 2 : 0) | (b1 ? 1 : 0)) + half;

    const int warp0   = blockIdx.x * 8 + (threadIdx.x >> 5);
    const int wstride = gridDim.x * 8;

    // idp: lanes 0..15 index entity ids, lanes 16..31 relation ids.
    const int* idp = (lane < MNB) ? item_entities : (item_relations - MNB);

    // ---- Prologue: load the first row's ids ----
    int my_id = 0, iid = 0;
    if (warp0 < N) {
        my_id = __ldg(idp + warp0 * MNB + lane);
        iid   = __ldg(item_ids + warp0);
    }

    for (int row = warp0; row < N; row += wstride) {
        // ---- Prefetch next iteration's ids (overlaps this row's compute) ----
        const int nrow = row + wstride;
        int my_id_n = 0, iid_n = 0;
        if (nrow < N) {
            my_id_n = __ldg(idp + nrow * MNB + lane);
            iid_n   = __ldg(item_ids + nrow);
        }

        const float4 it = *(const float4*)(item_table + iid * DDIM + 4 * dlane);
        const __half2 it_h0 = __floats2half2_rn(it.x, it.y);
        const __half2 it_h1 = __floats2half2_rn(it.z, it.w);

        // ---- Phase 1: 8 paired gathers, pack to fp16 immediately ----
        __half2 ent_h[8][2];
#pragma unroll
        for (int i = 0; i < 8; i++) {
            const int eid = __shfl_sync(FULLMASK, my_id, 2 * i + half);
            const float4 e = *(const float4*)(entity_table + eid * DDIM + 4 * dlane);
            ent_h[i][0] = __floats2half2_rn(e.x, e.y);
            ent_h[i][1] = __floats2half2_rn(e.z, e.w);
        }

        // ---- Phase 1b: u-table loads + fp16 partial dots ----
        float pl[8];
#pragma unroll
        for (int i = 0; i < 8; i++) {
            const int rid = __shfl_sync(FULLMASK, my_id, MNB + 2 * i + half);
            const uint4 u = *(const uint4*)(g_uh + rid * 2 * DDIM + 8 * dlane);
            __half2 h1 = __hmul2(*(const __half2*)&u.x, it_h0);
            h1 = __hfma2(*(const __half2*)&u.y, it_h1, h1);
            __half2 h2 = __hmul2(*(const __half2*)&u.z, ent_h[i][0]);
            h2 = __hfma2(*(const __half2*)&u.w, ent_h[i][1], h2);
            h1 = __hadd2(h1, h2);
            const float2 pf = __half22float2(h1);
            pl[i] = pf.x + pf.y;
        }

        // ---- Phase 2: merge tree over lane bits {3,2,1}; butterfly bit 0.
        // Lane l ends with the 16-lane sum (within its half) of local value
        // idx = 4*b3 + 2*b2 + b1; global value v = 2*idx + half.
#pragma unroll
        for (int i = 0; i < 4; i++) {
            float a = pl[i]     + __shfl_xor_sync(FULLMASK, pl[i],     8);
            float b = pl[i + 4] + __shfl_xor_sync(FULLMASK, pl[i + 4], 8);
            pl[i] = b3 ? b : a;
        }
#pragma unroll
        for (int i = 0; i < 2; i++) {
            float a = pl[i]     + __shfl_xor_sync(FULLMASK, pl[i],     4);
            float b = pl[i + 2] + __shfl_xor_sync(FULLMASK, pl[i + 2], 4);
            pl[i] = b2 ? b : a;
        }
        float a0 = pl[0] + __shfl_xor_sync(FULLMASK, pl[0], 2);
        float b0 = pl[1] + __shfl_xor_sync(FULLMASK, pl[1], 2);
        float e = b1 ? b0 : a0;
        e += __shfl_xor_sync(FULLMASK, e, 1);

        // ---- Epilogue: one logit per lane for its value v ----
        const int rid_v = __shfl_sync(FULLMASK, my_id, MNB + v);
        const int eid_v = __shfl_sync(FULLMASK, my_id, v);
        e += __ldg(g_c + rid_v);
        e = (e > 0.f) ? e : ALPHA * e;                    // leaky_relu
        e = (eid_v != NUM_ENTITIES) ? e : NEG_INF;        // padding mask

        // Softmax over the 16 distinct values: v spans lane bits {1,2,3,4},
        // duplicated over bit 0 -> reduce offsets {2,4,8,16}.
        float mx = e;
        mx = fmaxf(mx, __shfl_xor_sync(FULLMASK, mx, 2));
        mx = fmaxf(mx, __shfl_xor_sync(FULLMASK, mx, 4));
        mx = fmaxf(mx, __shfl_xor_sync(FULLMASK, mx, 8));
        mx = fmaxf(mx, __shfl_xor_sync(FULLMASK, mx, 16));
        const float ex = __expf(e - mx);
        float s = ex;
        s += __shfl_xor_sync(FULLMASK, s, 2);
        s += __shfl_xor_sync(FULLMASK, s, 4);
        s += __shfl_xor_sync(FULLMASK, s, 8);
        s += __shfl_xor_sync(FULLMASK, s, 16);
        const float w = __fdividef(ex, s);  // lane l: weight of its value v

        // ---- Weighted sum (fp32) over this half's 8 entities ----
        // Weight of global value 2i+half lives on the lane whose tree bits
        // encode idx=i in tree order (MSB of i on lane bit 3).
        float4 acc = make_float4(0.f, 0.f, 0.f, 0.f);
#pragma unroll
        for (int i = 0; i < 8; i++) {
            const int ii = (((i >> 2) & 1) << 3) | (((i >> 1) & 1) << 2) | ((i & 1) << 1);
            const float wm = __shfl_sync(FULLMASK, w, ii + (lane & 16));
            const float2 exy = __half22float2(ent_h[i][0]);
            const float2 ezw = __half22float2(ent_h[i][1]);
            acc.x = fmaf(wm, exy.x, acc.x);
            acc.y = fmaf(wm, exy.y, acc.y);
            acc.z = fmaf(wm, ezw.x, acc.z);
            acc.w = fmaf(wm, ezw.y, acc.w);
        }

        // Combine even/odd halves (lane l <-> l^16 same dims) + residual.
        acc.x += __shfl_xor_sync(FULLMASK, acc.x, 16);
        acc.y += __shfl_xor_sync(FULLMASK, acc.y, 16);
        acc.z += __shfl_xor_sync(FULLMASK, acc.z, 16);
        acc.w += __shfl_xor_sync(FULLMASK, acc.w, 16);
        if (lane < 16) {
            acc.x += it.x; acc.y += it.y; acc.z += it.z; acc.w += it.w;
            *(float4*)(out + row * DDIM + 4 * dlane) = acc;
        }

        // Rotate prefetched ids into place.
        my_id = my_id_n;
        iid   = iid_n;
    }
}

extern "C" void kernel_launch(void* const* d_in, const int* in_sizes, int n_in,
                              void* d_out, int out_size) {
    const int*   item_ids       = (const int*)d_in[0];
    const int*   item_entities  = (const int*)d_in[1];
    const int*   item_relations = (const int*)d_in[2];
    const float* item_table     = (const float*)d_in[3];
    const float* entity_table   = (const float*)d_in[4];
    const float* relation_table = (const float*)d_in[5];
    const float* fc_W           = (const float*)d_in[6];
    const float* fc_b           = (const float*)d_in[7];
    float* out = (float*)d_out;

    const int N = in_sizes[0];

    precompute_kernel<<<NREL, DDIM>>>(fc_W, fc_b, relation_table);

    // Persistent grid-stride: 4 blocks/SM x 148 SMs.
    gat_kernel<<<592, 256>>>(item_ids, item_entities, item_relations,
                             item_table, entity_table, out, N);
}